// round 15
// baseline (speedup 1.0000x reference)
#include <cuda_runtime.h>

#define BATCH 2048
#define TSTEPS 500
#define NIN 64
#define BT (BATCH * TSTEPS)

#define CH 20                    // timesteps per chunk
#define NCH (TSTEPS / CH)        // 25 chunks
#define PHASES (NCH + 1)         // 26 phases (pipeline fill + drain)
#define BPB 32                   // batch elements per block
#define ROWS_PER_CHUNK (CH * BPB)        // 640
#define PAIRS_PER_CHUNK (ROWS_PER_CHUNK / 2)  // 320

// ---------------------------------------------------------------------------
// One Euler step of the Izhikevich neuron (matches reference semantics:
// u update uses OLD v; v reset to c on spike; u += d on spike).
// Arithmetic identical to the R6-passing kernel (rel_err 5.9e-9).
// ---------------------------------------------------------------------------
__device__ __forceinline__ float izh(float& v, float& u, float I,
                                     float a, float bb, float c, float d) {
    float vn = v + 0.25f * (0.04f * v * v + 5.0f * v + 140.0f - u + I);
    float un = u + 0.25f * a * (bb * v - u);
    bool sp = (vn >= 30.0f);
    float z = sp ? 1.0f : 0.0f;
    v = sp ? c : vn;
    u = un + z * d;
    return z;
}

// ---------------------------------------------------------------------------
// Fused kernel: 64 blocks x 256 threads. Warp 0 scans 32 batch elements
// (one per lane); warps 1-7 produce the input rowsums for those 32 batch
// elements into a double-buffered shared ring, one 20-step chunk ahead.
// Phase k: producers fill chunk k into buf[k&1]; consumer scans chunk k-1
// from buf[(k-1)&1]; __syncthreads() separates phases. The 262MB input read
// is thereby hidden behind the scan instead of preceding it.
// ---------------------------------------------------------------------------
__global__ void __launch_bounds__(256, 1)
fused_kernel(const float* __restrict__ in,
             const float* __restrict__ w_in,
             float* __restrict__ out) {
    __shared__ float S_sh[2][CH][BPB];

    const int tid  = threadIdx.x;
    const int wid  = tid >> 5;
    const int lane = tid & 31;
    const int b0   = blockIdx.x * BPB;

    // ---- consumer state (warp 0 only; lane = local batch index) ----
    float w[24];
    float vL, uL, zL, vE, uE, vI, uI, vT, uT, zT, vM, uM;
    float vL2, uL2, zL2, vE2, uE2, vI2, uI2, vT2, uT2, zT2, vM2, uM2;
    float *o0, *o1, *o2, *o3, *o4, *o5;
    size_t base_bt = 0;

    if (wid == 0) {
#pragma unroll
        for (int i = 0; i < 24; i++) w[i] = __ldg(w_in + i);
        vL = -70.f; uL = -14.f; zL = 0.f;
        vE = -64.f; uE = -16.f;
        vI = -64.f; uI = -16.f;
        vT = -70.f; uT = -14.f; zT = 0.f;
        vM = -64.f; uM = -16.f;
        vL2 = -70.f; uL2 = -14.f; zL2 = 0.f;
        vE2 = -64.f; uE2 = -16.f;
        vI2 = -64.f; uI2 = -16.f;
        vT2 = -70.f; uT2 = -14.f; zT2 = 0.f;
        vM2 = -64.f; uM2 = -16.f;
        o0 = out;
        o1 = out + (size_t)BT;
        o2 = out + (size_t)2 * BT;
        o3 = out + (size_t)3 * BT;
        o4 = out + (size_t)4 * BT;   // o_spikes_o [B,T,4]
        o5 = out + (size_t)8 * BT;   // v_o        [B,T,4]
        base_bt = (size_t)(b0 + lane) * TSTEPS;
    }

    const float4* in4 = reinterpret_cast<const float4*>(in);
    const int half = lane >> 4;        // 0: row 2p, 1: row 2p+1
    const int l16  = lane & 15;

    for (int phase = 0; phase < PHASES; phase++) {
        // ---------------- producers: fill chunk `phase` ----------------
        if (wid != 0 && phase < NCH) {
            const int buf = phase & 1;
            const int t0  = phase * CH;
            const int pw  = wid - 1;   // 0..6
#pragma unroll 2
            for (int pr = pw; pr < PAIRS_PER_CHUNK; pr += 7) {
                int r  = pr * 2 + half;        // row within chunk, 0..639
                int tl = r >> 5;               // t_local 0..CH-1
                int bl = r & 31;               // b_local 0..31
                // row (b0+bl, t0+tl): 64 floats = 16 float4; 16 lanes cover it
                const float4* rp = in4 +
                    ((size_t)(b0 + bl) * TSTEPS + (size_t)(t0 + tl)) * 16 + l16;
                float4 v4 = __ldcs(rp);
                float s = (v4.x + v4.y) + (v4.z + v4.w);
                s += __shfl_xor_sync(0xffffffffu, s, 8);
                s += __shfl_xor_sync(0xffffffffu, s, 4);
                s += __shfl_xor_sync(0xffffffffu, s, 2);
                s += __shfl_xor_sync(0xffffffffu, s, 1);
                if (l16 == 0) S_sh[buf][tl][bl] = s;
            }
        }

        // ---------------- consumer: scan chunk `phase-1` ----------------
        if (wid == 0 && phase >= 1) {
            const int c   = phase - 1;
            const int buf = c & 1;
            const int t0c = c * CH;
#pragma unroll
            for (int g = 0; g < CH / 4; g++) {
                float a0[4], a1[4], a2[4], a3[4];
#pragma unroll
                for (int j = 0; j < 4; j++) {
                    int tl = g * 4 + j;
                    float S = S_sh[buf][tl][lane];
                    float zp  = w[0]  * S;
                    float zp2 = w[12] * S;

                    // --- channel 1 ---
                    float z2 = izh(vL, uL, w[2] * (zp * w[1]) + w[3] * zL,
                                   0.02f, 0.20f, -65.0f, 6.0f);
                    float z3 = izh(vE, uE, zp * w[4] + z2 * w[5],
                                   0.02f, 0.25f, -55.0f, 0.05f);
                    float z4 = izh(vI, uI, z3 * w[6],
                                   0.02f, 0.25f, -65.0f, 6.0f);
                    float z5 = izh(vT, uT, w[9] * (z3 * w[8]) + w[10] * zT,
                                   0.02f, 0.20f, -50.0f, 2.0f);
                    float z6 = izh(vM, uM, z5 * w[11],
                                   0.02f, 0.25f, -65.0f, 6.0f);
                    zL = z2; zT = z5;

                    // --- channel 2 (independent chain: ILP) ---
                    float z22 = izh(vL2, uL2, w[2] * (zp2 * w[13]) + w[3] * zL2,
                                    0.02f, 0.20f, -65.0f, 6.0f);
                    float z32 = izh(vE2, uE2, zp2 * w[16] + z22 * w[17],
                                    0.02f, 0.25f, -55.0f, 0.05f);
                    float z42 = izh(vI2, uI2, z32 * w[18],
                                    0.02f, 0.25f, -65.0f, 6.0f);
                    float z52 = izh(vT2, uT2, w[9] * (z32 * w[20]) + w[10] * zT2,
                                    0.02f, 0.20f, -50.0f, 2.0f);
                    float z62 = izh(vM2, uM2, z52 * w[23],
                                    0.02f, 0.25f, -65.0f, 6.0f);
                    zL2 = z22; zT2 = z52;

                    a0[j] = z6;  a1[j] = vM;
                    a2[j] = z62; a3[j] = vM2;

                    size_t bt4 = (base_bt + (size_t)(t0c + tl)) * 4;
                    __stcs(reinterpret_cast<float4*>(o4 + bt4),
                           make_float4(z2, z3, z4, z5));
                    __stcs(reinterpret_cast<float4*>(o5 + bt4),
                           make_float4(vL, vE, vI, vT));
                }
                size_t base = base_bt + (size_t)(t0c + g * 4);
                __stcs(reinterpret_cast<float4*>(o0 + base),
                       make_float4(a0[0], a0[1], a0[2], a0[3]));
                __stcs(reinterpret_cast<float4*>(o1 + base),
                       make_float4(a1[0], a1[1], a1[2], a1[3]));
                __stcs(reinterpret_cast<float4*>(o2 + base),
                       make_float4(a2[0], a2[1], a2[2], a2[3]));
                __stcs(reinterpret_cast<float4*>(o3 + base),
                       make_float4(a3[0], a3[1], a3[2], a3[3]));
            }
        }

        __syncthreads();   // phase boundary: all 256 threads
    }
}

extern "C" void kernel_launch(void* const* d_in, const int* in_sizes, int n_in,
                              void* d_out, int out_size) {
    const float* input = (const float*)d_in[0];   // [B,T,N] float32
    const float* wts   = (const float*)d_in[1];   // [24] float32
    float* out = (float*)d_out;                   // 12*B*T float32

    fused_kernel<<<BATCH / BPB, 256>>>(input, wts, out);
}